// round 14
// baseline (speedup 1.0000x reference)
#include <cuda_runtime.h>
#include <cuda_fp16.h>
#include <math.h>
#include <stdint.h>

// Problem dims
#define Bn   256
#define Sn   512
#define ENCn 256
#define DECn 256
#define ATTNn 128
#define Hn   48
#define G4   1024          // 4*DEC
#define KIH  257           // 1+ENC
#define KC2  576           // 1 + 256 ctx + 256 h + 63 pad  (fp16 concat K)
#define KQ   144           // split-K quarter (9 k-steps of 16)
#define NSPLIT 4

// ---------------- scratch (device globals; no allocation) ----------------
__device__ __half g_enc16[(size_t)Bn * Sn * ENCn];   // fp16 enc_outputs
__device__ __half g_ep16[(size_t)Bn * Sn * ATTNn];   // fp16 enc_proj
__device__ __half g_wenc16[ENCn * ATTNn];            // fp16 W_enc [K][N]
__device__ __half g_wdec16[DECn * ATTNn];            // fp16 W_dec [K][N]
__device__ float  g_c[Bn * DECn];
__device__ __half g_cat16[Bn * KC2];                 // 0=inp, 1..256=ctx, 257..512=h, pad
__device__ __half g_wcat16[G4 * KC2];                // [W_ih | W_hh] fp16, zero-padded
__device__ float  g_gp[NSPLIT * Bn * G4];            // split-K fp32 partials

__device__ __forceinline__ float tanh_ap(float x) {
    float y;
    asm("tanh.approx.f32 %0, %1;" : "=f"(y) : "f"(x));
    return y;
}

// PDL helpers: trigger lets the NEXT kernel begin its launch/prologue now;
// dependency-sync blocks until the PREVIOUS kernel fully completed (memory visible).
__device__ __forceinline__ void pdl_entry() {
    cudaTriggerProgrammaticLaunchCompletion();
    cudaGridDependencySynchronize();
}

// ---------------- mma helpers ----------------
__device__ __forceinline__ void ldsm_x4(uint32_t* r, const __half* p) {
    uint32_t a = (uint32_t)__cvta_generic_to_shared(p);
    asm volatile("ldmatrix.sync.aligned.m8n8.x4.shared.b16 {%0,%1,%2,%3}, [%4];"
                 : "=r"(r[0]), "=r"(r[1]), "=r"(r[2]), "=r"(r[3]) : "r"(a));
}
__device__ __forceinline__ void ldsm_x4_t(uint32_t* r, const __half* p) {
    uint32_t a = (uint32_t)__cvta_generic_to_shared(p);
    asm volatile("ldmatrix.sync.aligned.m8n8.x4.trans.shared.b16 {%0,%1,%2,%3}, [%4];"
                 : "=r"(r[0]), "=r"(r[1]), "=r"(r[2]), "=r"(r[3]) : "r"(a));
}
__device__ __forceinline__ void mma16816(float* d, const uint32_t* a, uint32_t b0, uint32_t b1) {
    asm volatile("mma.sync.aligned.m16n8k16.row.col.f32.f16.f16.f32 "
                 "{%0,%1,%2,%3}, {%4,%5,%6,%7}, {%8,%9}, {%0,%1,%2,%3};"
                 : "+f"(d[0]), "+f"(d[1]), "+f"(d[2]), "+f"(d[3])
                 : "r"(a[0]), "r"(a[1]), "r"(a[2]), "r"(a[3]), "r"(b0), "r"(b1));
}

// ---------------- init ----------------
__global__ void k_init(const float* __restrict__ h0, const float* __restrict__ c0,
                       const float* __restrict__ W_ih, const float* __restrict__ W_hh,
                       const float* __restrict__ enc, const float* __restrict__ Wenc,
                       const float* __restrict__ Wdec) {
    pdl_entry();
    size_t i0 = (size_t)blockIdx.x * blockDim.x + threadIdx.x;
    size_t stride = (size_t)gridDim.x * blockDim.x;
    for (size_t i = i0; i < Bn * DECn; i += stride) g_c[i] = c0[i];
    for (size_t i = i0; i < (size_t)Bn * KC2; i += stride) {
        int b = (int)(i / KC2), k = (int)(i % KC2);
        float w = (k >= KIH && k < KIH + DECn) ? h0[b * DECn + (k - KIH)] : 0.f;
        g_cat16[i] = __float2half(w);
    }
    for (size_t i = i0; i < (size_t)G4 * KC2; i += stride) {
        int r = (int)(i / KC2), k = (int)(i % KC2);
        float w = 0.f;
        if (k < KIH) w = W_ih[r * KIH + k];
        else if (k < KIH + DECn) w = W_hh[r * DECn + (k - KIH)];
        g_wcat16[i] = __float2half(w);
    }
    for (size_t i = i0; i < (size_t)Bn * Sn * ENCn / 2; i += stride) {
        float2 f = *((const float2*)enc + i);
        *((__half2*)g_enc16 + i) = __floats2half2_rn(f.x, f.y);
    }
    for (size_t i = i0; i < (size_t)ENCn * ATTNn / 2; i += stride) {
        float2 f = *((const float2*)Wenc + i);
        *((__half2*)g_wenc16 + i) = __floats2half2_rn(f.x, f.y);
    }
    for (size_t i = i0; i < (size_t)DECn * ATTNn / 2; i += stride) {
        float2 f = *((const float2*)Wdec + i);
        *((__half2*)g_wdec16 + i) = __floats2half2_rn(f.x, f.y);
    }
}

// ---------------- K0: enc_proj via fp16 tensor cores ----------------
#define LDA 72    // As row stride (halfs)
#define LDB 136   // Bs row stride (halfs)
__global__ __launch_bounds__(256) void k_encproj() {
    pdl_entry();
    __shared__ __half As[128 * LDA];
    __shared__ __half Bs[64 * LDB];
    int tid = threadIdx.x;
    int wid = tid >> 5, l = tid & 31;
    int warp_m = wid & 3, warp_n = wid >> 2;       // 4 x 2 warps; warp tile 32m x 64n
    size_t m0 = (size_t)blockIdx.x * 128;

    float acc[2][8][4];
#pragma unroll
    for (int i = 0; i < 2; i++)
#pragma unroll
        for (int j = 0; j < 8; j++)
#pragma unroll
            for (int q = 0; q < 4; q++) acc[i][j][q] = 0.f;

    for (int kc = 0; kc < 4; kc++) {
#pragma unroll
        for (int it = 0; it < 4; it++) {
            int i = tid + 256 * it;
            int r = i >> 3, c = (i & 7) * 8;
            *(uint4*)&As[r * LDA + c] = *(const uint4*)&g_enc16[(m0 + r) * ENCn + kc * 64 + c];
        }
#pragma unroll
        for (int it = 0; it < 4; it++) {
            int i = tid + 256 * it;
            int r = i >> 4, c = (i & 15) * 8;
            *(uint4*)&Bs[r * LDB + c] = *(const uint4*)&g_wenc16[(size_t)(kc * 64 + r) * ATTNn + c];
        }
        __syncthreads();
#pragma unroll
        for (int ks = 0; ks < 4; ks++) {
            uint32_t a[2][4];
#pragma unroll
            for (int mt = 0; mt < 2; mt++)
                ldsm_x4(a[mt], &As[(warp_m * 32 + mt * 16 + (l & 15)) * LDA + ks * 16 + (l >> 4) * 8]);
            uint32_t bf[4][4];
#pragma unroll
            for (int pr = 0; pr < 4; pr++)
                ldsm_x4_t(bf[pr], &Bs[(ks * 16 + (l & 15)) * LDB + warp_n * 64 + pr * 16 + (l >> 4) * 8]);
#pragma unroll
            for (int mt = 0; mt < 2; mt++)
#pragma unroll
                for (int nt = 0; nt < 8; nt++)
                    mma16816(acc[mt][nt], a[mt], bf[nt >> 1][(nt & 1) * 2], bf[nt >> 1][(nt & 1) * 2 + 1]);
        }
        __syncthreads();
    }
    int r0 = l >> 2, c0 = (l & 3) * 2;
#pragma unroll
    for (int mt = 0; mt < 2; mt++)
#pragma unroll
        for (int nt = 0; nt < 8; nt++) {
            size_t gm = m0 + warp_m * 32 + mt * 16 + r0;
            int gn = warp_n * 64 + nt * 8 + c0;
            *(__half2*)&g_ep16[gm * ATTNn + gn]       = __floats2half2_rn(acc[mt][nt][0], acc[mt][nt][1]);
            *(__half2*)&g_ep16[(gm + 8) * ATTNn + gn] = __floats2half2_rn(acc[mt][nt][2], acc[mt][nt][3]);
        }
}

// ---------------- K1: fused [cell(t-1)] + attention(t), one block per batch b
__global__ __launch_bounds__(512, 2) void k_attn(const float* __restrict__ v,
                                                 const float* __restrict__ bih,
                                                 const float* __restrict__ bhh,
                                                 const float* __restrict__ Wout,
                                                 const float* __restrict__ bout,
                                                 float* __restrict__ out, int t) {
    pdl_entry();   // wait on gates(t-1) results (g_gp) / encproj
    int b = blockIdx.x;
    int tid = threadIdx.x;
    __shared__ float sh_h[DECn];
    __shared__ float sh_dpp[8][ATTNn];
    __shared__ float sh_dp[ATTNn];
    __shared__ float sh_v[ATTNn];
    __shared__ float sh_sc[Sn];
    __shared__ float sh_red[32];
    __shared__ float sh_cx[3][ENCn];

    // ---- fused LSTM cell for step t-1 ----
    if (t > 0) {
        if (tid < DECn) {
            int d = tid;
            float gi = bih[d]       + bhh[d];
            float gf = bih[d + 256] + bhh[d + 256];
            float gg = bih[d + 512] + bhh[d + 512];
            float go = bih[d + 768] + bhh[d + 768];
#pragma unroll
            for (int z = 0; z < NSPLIT; z++) {
                const float* gp = g_gp + (size_t)z * Bn * G4 + b * G4 + d;
                gi += gp[0]; gf += gp[256]; gg += gp[512]; go += gp[768];
            }
            float si = 1.f / (1.f + __expf(-gi));
            float sf = 1.f / (1.f + __expf(-gf));
            float so = 1.f / (1.f + __expf(-go));
            float cn = sf * g_c[b * DECn + d] + si * tanhf(gg);
            float hn = so * tanhf(cn);
            g_c[b * DECn + d] = cn;
            sh_h[d] = hn;
            g_cat16[b * KC2 + KIH + d] = __float2half(hn);
            float p = hn * Wout[d];
#pragma unroll
            for (int o = 16; o; o >>= 1) p += __shfl_xor_sync(0xFFFFFFFFu, p, o);
            if ((d & 31) == 0) sh_red[d >> 5] = p;
        }
        __syncthreads();
        if (tid == 0) {
            float s = 0.f;
#pragma unroll
            for (int i = 0; i < 8; i++) s += sh_red[i];
            s += bout[0];
            out[b * Hn + (t - 1)] = s;
            g_cat16[b * KC2] = __float2half(s);
        }
    } else {
        if (tid < DECn) sh_h[tid] = __half2float(g_cat16[b * KC2 + KIH + tid]);
    }
    if (tid < ATTNn) sh_v[tid] = v[tid];
    __syncthreads();

    // ---- dec_proj = h @ W_dec (fp16 weights, 8-way K split, 2 cols/thread) ----
    {
        int c2 = (tid & 63) * 2, part = tid >> 6;       // part 0..7, 32 k each
        float2 a = make_float2(0.f, 0.f);
#pragma unroll 8
        for (int k = part * 32; k < part * 32 + 32; k++) {
            float2 w = __half22float2(*(const __half2*)&g_wdec16[k * ATTNn + c2]);
            float hk = sh_h[k];
            a.x = fmaf(hk, w.x, a.x);
            a.y = fmaf(hk, w.y, a.y);
        }
        sh_dpp[part][c2] = a.x; sh_dpp[part][c2 + 1] = a.y;
    }
    __syncthreads();
    if (tid < ATTNn) {
        float s = 0.f;
#pragma unroll
        for (int i = 0; i < 8; i++) s += sh_dpp[i][tid];
        sh_dp[tid] = s;
    }
    __syncthreads();

    // ---- scores: warp handles 2 s per pass; 16 lanes x 8 dims each; prefetched ----
    int w = tid >> 5, l = tid & 31;
    {
        int sgrp = l >> 4;            // which of 2 s in this pass
        int dlo = (l & 15) * 8;       // my 8 attn dims
        float dpr[8], vr[8];
        *(float4*)&dpr[0] = *(float4*)&sh_dp[dlo];
        *(float4*)&dpr[4] = *(float4*)&sh_dp[dlo + 4];
        *(float4*)&vr[0]  = *(float4*)&sh_v[dlo];
        *(float4*)&vr[4]  = *(float4*)&sh_v[dlo + 4];
        const __half* epb = g_ep16 + (size_t)b * Sn * ATTNn + dlo;

        int s = w * 2 + sgrp;
        uint4 u = *(const uint4*)(epb + (size_t)s * ATTNn);
#pragma unroll
        for (int p = 0; p < 16; p++) {
            uint4 un;
            if (p < 15) un = *(const uint4*)(epb + (size_t)(s + 32) * ATTNn);   // prefetch next pass
            const __half2* hp = (const __half2*)&u;
            float sc = 0.f;
#pragma unroll
            for (int j = 0; j < 4; j++) {
                float2 f = __half22float2(hp[j]);
                sc = fmaf(tanh_ap(f.x + dpr[2 * j]),     vr[2 * j],     sc);
                sc = fmaf(tanh_ap(f.y + dpr[2 * j + 1]), vr[2 * j + 1], sc);
            }
            sc += __shfl_xor_sync(0xFFFFFFFFu, sc, 8);
            sc += __shfl_xor_sync(0xFFFFFFFFu, sc, 4);
            sc += __shfl_xor_sync(0xFFFFFFFFu, sc, 2);
            sc += __shfl_xor_sync(0xFFFFFFFFu, sc, 1);
            if ((l & 15) == 0) sh_sc[s] = sc;
            u = un;
            s += 32;
        }
    }
    __syncthreads();

    // ---- softmax over 512 (scores bounded by sum|v| ~ 5; no max pass needed) ----
    float e = __expf(sh_sc[tid]);
    float ssum = e;
#pragma unroll
    for (int o = 16; o; o >>= 1) ssum += __shfl_xor_sync(0xFFFFFFFFu, ssum, o);
    if (l == 0) sh_red[w] = ssum;
    __syncthreads();
    float tot = 0.f;
#pragma unroll
    for (int i = 0; i < 16; i++) tot += sh_red[i];
    float wgt = e / tot;
    sh_sc[tid] = wgt;
    out[(size_t)Bn * Hn + ((size_t)b * Hn + t) * Sn + tid] = wgt;
    __syncthreads();

    // ---- context = attn_w @ enc_outputs (fp16), 2 dims/thread, 4-way s split ----
    {
        int j = tid & 127, part = tid >> 7;
        const __half* eb = g_enc16 + (size_t)b * Sn * ENCn + 2 * j;
        float2 acc = make_float2(0.f, 0.f);
#pragma unroll 8
        for (int s = part; s < Sn; s += 4) {
            float2 f = __half22float2(*(const __half2*)(eb + (size_t)s * ENCn));
            float ww = sh_sc[s];
            acc.x = fmaf(ww, f.x, acc.x);
            acc.y = fmaf(ww, f.y, acc.y);
        }
        if (part > 0) { sh_cx[part - 1][2 * j] = acc.x; sh_cx[part - 1][2 * j + 1] = acc.y; }
        __syncthreads();
        if (part == 0) {
            float c0v = acc.x + sh_cx[0][2 * j] + sh_cx[1][2 * j] + sh_cx[2][2 * j];
            float c1v = acc.y + sh_cx[0][2 * j + 1] + sh_cx[1][2 * j + 1] + sh_cx[2][2 * j + 1];
            // scalar half stores (odd half index -> half2 store would be misaligned)
            g_cat16[b * KC2 + 1 + 2 * j]     = __float2half(c0v);
            g_cat16[b * KC2 + 1 + 2 * j + 1] = __float2half(c1v);
        }
    }
}

// ---------------- K2: gates, single-shot panel, grid 4m x 16n x 4z = 256 blocks
// tile: cat[gm0:+64, gkb:+144] @ wcat[gn0:+64, gkb:+144]^T  (fp16 mma, fp32 acc)
#define LDS_G 144   // smem row stride in halfs (288B rows; ldsm addrs 16B aligned)
__global__ __launch_bounds__(256) void k_gates256() {
    pdl_entry();   // wait on attn(t) writes to g_cat16
    __shared__ __half gAs[64 * LDS_G];
    __shared__ __half gBs[64 * LDS_G];
    int tid = threadIdx.x;
    int w = tid >> 5, l = tid & 31;
    int gm0 = blockIdx.x * 64, gn0 = blockIdx.y * 64;
    int gz = blockIdx.z, gkb = gz * KQ;
    int gwarp_m = w & 3, gwarp_n = w >> 2;      // 4m x 2n warps; warp tile 16m x 32n

    // single-shot panel load: 2304 uint4 (A 1152 + B 1152), 9 per thread, MLP ~9
#pragma unroll
    for (int it = 0; it < 9; it++) {
        int i = tid + 256 * it;
        int reg = i >= 1152;
        int j = reg ? i - 1152 : i;
        int r = j / 18, c = j % 18;
        const __half* src = reg
            ? g_wcat16 + (size_t)(gn0 + r) * KC2 + gkb + c * 8
            : g_cat16  + (size_t)(gm0 + r) * KC2 + gkb + c * 8;
        __half* dst = (reg ? gBs : gAs) + r * LDS_G + c * 8;
        *(uint4*)dst = *(const uint4*)src;
    }
    __syncthreads();

    float acc[4][4];
#pragma unroll
    for (int i = 0; i < 4; i++)
#pragma unroll
        for (int q = 0; q < 4; q++) acc[i][q] = 0.f;

#pragma unroll
    for (int ks = 0; ks < 9; ks++) {
        uint32_t a[4], bq[2][4];
        ldsm_x4(a, &gAs[(gwarp_m * 16 + (l & 15)) * LDS_G + ks * 16 + (l >> 4) * 8]);
#pragma unroll
        for (int bt = 0; bt < 2; bt++)
            ldsm_x4(bq[bt], &gBs[(gwarp_n * 32 + bt * 16 + (l & 15)) * LDS_G + ks * 16 + (l >> 4) * 8]);
#pragma unroll
        for (int bt = 0; bt < 2; bt++) {
            mma16816(acc[bt * 2 + 0], a, bq[bt][0], bq[bt][2]);   // n 0-7 of sub-tile
            mma16816(acc[bt * 2 + 1], a, bq[bt][1], bq[bt][3]);   // n 8-15
        }
    }

    float* Cg = g_gp + (size_t)gz * Bn * G4;
    int r0 = l >> 2, c0 = (l & 3) * 2;
#pragma unroll
    for (int nt = 0; nt < 4; nt++) {
        int gmr = gm0 + gwarp_m * 16 + r0;
        int gnc = gn0 + gwarp_n * 32 + (nt >> 1) * 16 + (nt & 1) * 8 + c0;
        *(float2*)&Cg[(size_t)gmr * G4 + gnc]       = make_float2(acc[nt][0], acc[nt][1]);
        *(float2*)&Cg[(size_t)(gmr + 8) * G4 + gnc] = make_float2(acc[nt][2], acc[nt][3]);
    }
}

// ---------------- K3: final cell for last step's preds ----------------
__global__ __launch_bounds__(256) void k_cell_final(const float* __restrict__ bih,
                                                    const float* __restrict__ bhh,
                                                    const float* __restrict__ Wout,
                                                    const float* __restrict__ bout,
                                                    float* __restrict__ out) {
    pdl_entry();
    int b = blockIdx.x, d = threadIdx.x;
    float gi = bih[d]       + bhh[d];
    float gf = bih[d + 256] + bhh[d + 256];
    float gg = bih[d + 512] + bhh[d + 512];
    float go = bih[d + 768] + bhh[d + 768];
#pragma unroll
    for (int z = 0; z < NSPLIT; z++) {
        const float* gp = g_gp + (size_t)z * Bn * G4 + b * G4 + d;
        gi += gp[0]; gf += gp[256]; gg += gp[512]; go += gp[768];
    }
    float si = 1.f / (1.f + __expf(-gi));
    float sf = 1.f / (1.f + __expf(-gf));
    float so = 1.f / (1.f + __expf(-go));
    float cn = sf * g_c[b * DECn + d] + si * tanhf(gg);
    float hn = so * tanhf(cn);
    float p = hn * Wout[d];
    __shared__ float sred[8];
#pragma unroll
    for (int o = 16; o; o >>= 1) p += __shfl_xor_sync(0xFFFFFFFFu, p, o);
    if ((d & 31) == 0) sred[d >> 5] = p;
    __syncthreads();
    if (d == 0) {
        float s = 0.f;
#pragma unroll
        for (int i = 0; i < 8; i++) s += sred[i];
        out[b * Hn + (Hn - 1)] = s + bout[0];
    }
}

// ---------------- launch (all edges PDL) ----------------
extern "C" void kernel_launch(void* const* d_in, const int* in_sizes, int n_in,
                              void* d_out, int out_size) {
    (void)in_sizes; (void)n_in; (void)out_size;
    const float* enc  = (const float*)d_in[0];
    const float* h0   = (const float*)d_in[1];
    const float* c0   = (const float*)d_in[2];
    const float* Wenc = (const float*)d_in[3];
    const float* Wdec = (const float*)d_in[4];
    const float* v    = (const float*)d_in[5];
    const float* Wih  = (const float*)d_in[6];
    const float* Whh  = (const float*)d_in[7];
    const float* bih  = (const float*)d_in[8];
    const float* bhh  = (const float*)d_in[9];
    const float* Wout = (const float*)d_in[10];
    const float* bout = (const float*)d_in[11];
    float* out = (float*)d_out;

    cudaLaunchAttribute at[1];
    at[0].id = cudaLaunchAttributeProgrammaticStreamSerialization;
    at[0].val.programmaticStreamSerializationAllowed = 1;

    cudaLaunchConfig_t cfg{};
    cfg.stream = 0;
    cfg.attrs = at;
    cfg.numAttrs = 1;
    cfg.dynamicSmemBytes = 0;

    cfg.gridDim = dim3(2048, 1, 1); cfg.blockDim = dim3(256, 1, 1);
    cudaLaunchKernelEx(&cfg, k_init, h0, c0, Wih, Whh, enc, Wenc, Wdec);

    cfg.gridDim = dim3((Bn * Sn) / 128, 1, 1); cfg.blockDim = dim3(256, 1, 1);
    cudaLaunchKernelEx(&cfg, k_encproj);

    for (int t = 0; t < Hn; t++) {
        cfg.gridDim = dim3(Bn, 1, 1); cfg.blockDim = dim3(512, 1, 1);
        cudaLaunchKernelEx(&cfg, k_attn, v, bih, bhh, Wout, bout, out, t);
        cfg.gridDim = dim3(4, 16, NSPLIT); cfg.blockDim = dim3(256, 1, 1);
        cudaLaunchKernelEx(&cfg, k_gates256);
    }
    cfg.gridDim = dim3(Bn, 1, 1); cfg.blockDim = dim3(256, 1, 1);
    cudaLaunchKernelEx(&cfg, k_cell_final, bih, bhh, Wout, bout, out);
}

// round 15
// speedup vs baseline: 1.0251x; 1.0251x over previous
#include <cuda_runtime.h>
#include <cuda_fp16.h>
#include <math.h>
#include <stdint.h>

// Problem dims
#define Bn   256
#define Sn   512
#define ENCn 256
#define DECn 256
#define ATTNn 128
#define Hn   48
#define G4   1024          // 4*DEC
#define KIH  257           // 1+ENC
#define KC2  576           // 1 + 256 ctx + 256 h + 63 pad  (fp16 concat K)
#define KQ   144           // split-K quarter (9 k-steps of 16)
#define NSPLIT 4

// ---------------- scratch (device globals; no allocation) ----------------
__device__ __half g_enc16[(size_t)Bn * Sn * ENCn];   // fp16 enc_outputs
__device__ __half g_ep16[(size_t)Bn * Sn * ATTNn];   // fp16 enc_proj
__device__ __half g_wenc16[ENCn * ATTNn];            // fp16 W_enc [K][N]
__device__ __half g_wdec16[DECn * ATTNn];            // fp16 W_dec [K][N]
__device__ float  g_c[Bn * DECn];
__device__ __half g_cat16[Bn * KC2];                 // 0=inp, 1..256=ctx, 257..512=h, pad
__device__ __half g_wcat16[G4 * KC2];                // [W_ih | W_hh] fp16, zero-padded
__device__ float  g_gp[NSPLIT * Bn * G4];            // split-K fp32 partials

__device__ __forceinline__ __half2 tanh_h2(__half2 x) {
    uint32_t r;
    asm("tanh.approx.f16x2 %0, %1;" : "=r"(r) : "r"(*(uint32_t*)&x));
    return *(__half2*)&r;
}

// ---------------- mma helpers ----------------
__device__ __forceinline__ void ldsm_x4(uint32_t* r, const __half* p) {
    uint32_t a = (uint32_t)__cvta_generic_to_shared(p);
    asm volatile("ldmatrix.sync.aligned.m8n8.x4.shared.b16 {%0,%1,%2,%3}, [%4];"
                 : "=r"(r[0]), "=r"(r[1]), "=r"(r[2]), "=r"(r[3]) : "r"(a));
}
__device__ __forceinline__ void ldsm_x4_t(uint32_t* r, const __half* p) {
    uint32_t a = (uint32_t)__cvta_generic_to_shared(p);
    asm volatile("ldmatrix.sync.aligned.m8n8.x4.trans.shared.b16 {%0,%1,%2,%3}, [%4];"
                 : "=r"(r[0]), "=r"(r[1]), "=r"(r[2]), "=r"(r[3]) : "r"(a));
}
__device__ __forceinline__ void mma16816(float* d, const uint32_t* a, uint32_t b0, uint32_t b1) {
    asm volatile("mma.sync.aligned.m16n8k16.row.col.f32.f16.f16.f32 "
                 "{%0,%1,%2,%3}, {%4,%5,%6,%7}, {%8,%9}, {%0,%1,%2,%3};"
                 : "+f"(d[0]), "+f"(d[1]), "+f"(d[2]), "+f"(d[3])
                 : "r"(a[0]), "r"(a[1]), "r"(a[2]), "r"(a[3]), "r"(b0), "r"(b1));
}

// ---------------- init ----------------
__global__ void k_init(const float* __restrict__ h0, const float* __restrict__ c0,
                       const float* __restrict__ W_ih, const float* __restrict__ W_hh,
                       const float* __restrict__ enc, const float* __restrict__ Wenc,
                       const float* __restrict__ Wdec) {
    size_t i0 = (size_t)blockIdx.x * blockDim.x + threadIdx.x;
    size_t stride = (size_t)gridDim.x * blockDim.x;
    for (size_t i = i0; i < Bn * DECn; i += stride) g_c[i] = c0[i];
    for (size_t i = i0; i < (size_t)Bn * KC2; i += stride) {
        int b = (int)(i / KC2), k = (int)(i % KC2);
        float w = (k >= KIH && k < KIH + DECn) ? h0[b * DECn + (k - KIH)] : 0.f;
        g_cat16[i] = __float2half(w);
    }
    for (size_t i = i0; i < (size_t)G4 * KC2; i += stride) {
        int r = (int)(i / KC2), k = (int)(i % KC2);
        float w = 0.f;
        if (k < KIH) w = W_ih[r * KIH + k];
        else if (k < KIH + DECn) w = W_hh[r * DECn + (k - KIH)];
        g_wcat16[i] = __float2half(w);
    }
    for (size_t i = i0; i < (size_t)Bn * Sn * ENCn / 2; i += stride) {
        float2 f = *((const float2*)enc + i);
        *((__half2*)g_enc16 + i) = __floats2half2_rn(f.x, f.y);
    }
    for (size_t i = i0; i < (size_t)ENCn * ATTNn / 2; i += stride) {
        float2 f = *((const float2*)Wenc + i);
        *((__half2*)g_wenc16 + i) = __floats2half2_rn(f.x, f.y);
    }
    for (size_t i = i0; i < (size_t)DECn * ATTNn / 2; i += stride) {
        float2 f = *((const float2*)Wdec + i);
        *((__half2*)g_wdec16 + i) = __floats2half2_rn(f.x, f.y);
    }
}

// ---------------- K0: enc_proj via fp16 tensor cores ----------------
#define LDA 72    // As row stride (halfs)
#define LDB 136   // Bs row stride (halfs)
__global__ __launch_bounds__(256) void k_encproj() {
    __shared__ __half As[128 * LDA];
    __shared__ __half Bs[64 * LDB];
    int tid = threadIdx.x;
    int wid = tid >> 5, l = tid & 31;
    int warp_m = wid & 3, warp_n = wid >> 2;       // 4 x 2 warps; warp tile 32m x 64n
    size_t m0 = (size_t)blockIdx.x * 128;

    float acc[2][8][4];
#pragma unroll
    for (int i = 0; i < 2; i++)
#pragma unroll
        for (int j = 0; j < 8; j++)
#pragma unroll
            for (int q = 0; q < 4; q++) acc[i][j][q] = 0.f;

    for (int kc = 0; kc < 4; kc++) {
#pragma unroll
        for (int it = 0; it < 4; it++) {
            int i = tid + 256 * it;
            int r = i >> 3, c = (i & 7) * 8;
            *(uint4*)&As[r * LDA + c] = *(const uint4*)&g_enc16[(m0 + r) * ENCn + kc * 64 + c];
        }
#pragma unroll
        for (int it = 0; it < 4; it++) {
            int i = tid + 256 * it;
            int r = i >> 4, c = (i & 15) * 8;
            *(uint4*)&Bs[r * LDB + c] = *(const uint4*)&g_wenc16[(size_t)(kc * 64 + r) * ATTNn + c];
        }
        __syncthreads();
#pragma unroll
        for (int ks = 0; ks < 4; ks++) {
            uint32_t a[2][4];
#pragma unroll
            for (int mt = 0; mt < 2; mt++)
                ldsm_x4(a[mt], &As[(warp_m * 32 + mt * 16 + (l & 15)) * LDA + ks * 16 + (l >> 4) * 8]);
            uint32_t bf[4][4];
#pragma unroll
            for (int pr = 0; pr < 4; pr++)
                ldsm_x4_t(bf[pr], &Bs[(ks * 16 + (l & 15)) * LDB + warp_n * 64 + pr * 16 + (l >> 4) * 8]);
#pragma unroll
            for (int mt = 0; mt < 2; mt++)
#pragma unroll
                for (int nt = 0; nt < 8; nt++)
                    mma16816(acc[mt][nt], a[mt], bf[nt >> 1][(nt & 1) * 2], bf[nt >> 1][(nt & 1) * 2 + 1]);
        }
        __syncthreads();
    }
    int r0 = l >> 2, c0 = (l & 3) * 2;
#pragma unroll
    for (int mt = 0; mt < 2; mt++)
#pragma unroll
        for (int nt = 0; nt < 8; nt++) {
            size_t gm = m0 + warp_m * 32 + mt * 16 + r0;
            int gn = warp_n * 64 + nt * 8 + c0;
            *(__half2*)&g_ep16[gm * ATTNn + gn]       = __floats2half2_rn(acc[mt][nt][0], acc[mt][nt][1]);
            *(__half2*)&g_ep16[(gm + 8) * ATTNn + gn] = __floats2half2_rn(acc[mt][nt][2], acc[mt][nt][3]);
        }
}

// ---------------- K1: fused [cell(t-1)] + attention(t), one block per batch b
__global__ __launch_bounds__(512, 2) void k_attn(const float* __restrict__ v,
                                                 const float* __restrict__ bih,
                                                 const float* __restrict__ bhh,
                                                 const float* __restrict__ Wout,
                                                 const float* __restrict__ bout,
                                                 float* __restrict__ out, int t) {
    int b = blockIdx.x;
    int tid = threadIdx.x;
    __shared__ float sh_h[DECn];
    __shared__ float sh_dpp[8][ATTNn];
    __shared__ __align__(16) __half sh_dph[ATTNn];
    __shared__ __align__(16) __half sh_vh[ATTNn];
    __shared__ float sh_sc[Sn];
    __shared__ float sh_red[32];
    __shared__ float sh_cp[16 * ENCn];    // context partials: 16 s-parts x 256 dims

    // ---- fused LSTM cell for step t-1 ----
    if (t > 0) {
        if (tid < DECn) {
            int d = tid;
            float gi = bih[d]       + bhh[d];
            float gf = bih[d + 256] + bhh[d + 256];
            float gg = bih[d + 512] + bhh[d + 512];
            float go = bih[d + 768] + bhh[d + 768];
#pragma unroll
            for (int z = 0; z < NSPLIT; z++) {
                const float* gp = g_gp + (size_t)z * Bn * G4 + b * G4 + d;
                gi += gp[0]; gf += gp[256]; gg += gp[512]; go += gp[768];
            }
            float si = 1.f / (1.f + __expf(-gi));
            float sf = 1.f / (1.f + __expf(-gf));
            float so = 1.f / (1.f + __expf(-go));
            float cn = sf * g_c[b * DECn + d] + si * tanhf(gg);
            float hn = so * tanhf(cn);
            g_c[b * DECn + d] = cn;
            sh_h[d] = hn;
            g_cat16[b * KC2 + KIH + d] = __float2half(hn);
            float p = hn * Wout[d];
#pragma unroll
            for (int o = 16; o; o >>= 1) p += __shfl_xor_sync(0xFFFFFFFFu, p, o);
            if ((d & 31) == 0) sh_red[d >> 5] = p;
        }
        __syncthreads();
        if (tid == 0) {
            float s = 0.f;
#pragma unroll
            for (int i = 0; i < 8; i++) s += sh_red[i];
            s += bout[0];
            out[b * Hn + (t - 1)] = s;
            g_cat16[b * KC2] = __float2half(s);
        }
    } else {
        if (tid < DECn) sh_h[tid] = __half2float(g_cat16[b * KC2 + KIH + tid]);
    }
    if (tid < ATTNn) sh_vh[tid] = __float2half(v[tid]);
    __syncthreads();

    // ---- dec_proj = h @ W_dec (fp16 weights, 8-way K split, 2 cols/thread) ----
    {
        int c2 = (tid & 63) * 2, part = tid >> 6;       // part 0..7, 32 k each
        float2 a = make_float2(0.f, 0.f);
#pragma unroll 8
        for (int k = part * 32; k < part * 32 + 32; k++) {
            float2 w = __half22float2(*(const __half2*)&g_wdec16[k * ATTNn + c2]);
            float hk = sh_h[k];
            a.x = fmaf(hk, w.x, a.x);
            a.y = fmaf(hk, w.y, a.y);
        }
        sh_dpp[part][c2] = a.x; sh_dpp[part][c2 + 1] = a.y;
    }
    __syncthreads();
    if (tid < ATTNn) {
        float s = 0.f;
#pragma unroll
        for (int i = 0; i < 8; i++) s += sh_dpp[i][tid];
        sh_dph[tid] = __float2half(s);
    }
    __syncthreads();

    // ---- scores (half2 math): warp handles 2 s per pass; 16 lanes x 8 dims ----
    int w = tid >> 5, l = tid & 31;
    {
        int sgrp = l >> 4;            // which of 2 s in this pass
        int dlo = (l & 15) * 8;       // my 8 attn dims
        uint4 ud = *(const uint4*)&sh_dph[dlo];
        uint4 uv = *(const uint4*)&sh_vh[dlo];
        const __half2* dp2 = (const __half2*)&ud;
        const __half2* v2  = (const __half2*)&uv;
        const __half* epb = g_ep16 + (size_t)b * Sn * ATTNn + dlo;

        int s = w * 2 + sgrp;
        uint4 u = *(const uint4*)(epb + (size_t)s * ATTNn);
#pragma unroll
        for (int p = 0; p < 16; p++) {
            uint4 un;
            if (p < 15) un = *(const uint4*)(epb + (size_t)(s + 32) * ATTNn);   // prefetch
            const __half2* hp = (const __half2*)&u;
            __half2 acc2 = __float2half2_rn(0.f);
#pragma unroll
            for (int j = 0; j < 4; j++)
                acc2 = __hfma2(tanh_h2(__hadd2(hp[j], dp2[j])), v2[j], acc2);
            float2 fs = __half22float2(acc2);
            float sc = fs.x + fs.y;
            sc += __shfl_xor_sync(0xFFFFFFFFu, sc, 8);
            sc += __shfl_xor_sync(0xFFFFFFFFu, sc, 4);
            sc += __shfl_xor_sync(0xFFFFFFFFu, sc, 2);
            sc += __shfl_xor_sync(0xFFFFFFFFu, sc, 1);
            if ((l & 15) == 0) sh_sc[s] = sc;
            u = un;
            s += 32;
        }
    }
    __syncthreads();

    // ---- softmax over 512 (scores bounded by sum|v| ~ 5; no max pass needed) ----
    float e = __expf(sh_sc[tid]);
    float ssum = e;
#pragma unroll
    for (int o = 16; o; o >>= 1) ssum += __shfl_xor_sync(0xFFFFFFFFu, ssum, o);
    if (l == 0) sh_red[w] = ssum;
    __syncthreads();
    float tot = 0.f;
#pragma unroll
    for (int i = 0; i < 16; i++) tot += sh_red[i];
    float wgt = e / tot;
    sh_sc[tid] = wgt;
    out[(size_t)Bn * Hn + ((size_t)b * Hn + t) * Sn + tid] = wgt;
    __syncthreads();

    // ---- context = attn_w @ enc_outputs: 8 dims/thread (LDG.128), 16-way s split,
    //      HFMA2 per-part accumulation, fp32 cross-part reduce ----
    {
        int dg = tid & 31;            // dim group: dims 8*dg .. 8*dg+7
        int part = tid >> 5;          // warp id = s-part 0..15
        const __half* eb = g_enc16 + (size_t)b * Sn * ENCn + 8 * dg;
        __half2 a0 = __float2half2_rn(0.f), a1 = a0, a2 = a0, a3 = a0;
#pragma unroll 8
        for (int s = part; s < Sn; s += 16) {
            uint4 u = *(const uint4*)(eb + (size_t)s * ENCn);
            __half2 w2 = __half2half2(__float2half(sh_sc[s]));
            const __half2* hp = (const __half2*)&u;
            a0 = __hfma2(hp[0], w2, a0);
            a1 = __hfma2(hp[1], w2, a1);
            a2 = __hfma2(hp[2], w2, a2);
            a3 = __hfma2(hp[3], w2, a3);
        }
        float2 f0 = __half22float2(a0), f1 = __half22float2(a1);
        float2 f2 = __half22float2(a2), f3 = __half22float2(a3);
        float* cp = sh_cp + part * ENCn + dg * 8;
        cp[0] = f0.x; cp[1] = f0.y; cp[2] = f1.x; cp[3] = f1.y;
        cp[4] = f2.x; cp[5] = f2.y; cp[6] = f3.x; cp[7] = f3.y;
        __syncthreads();
        if (tid < ENCn) {
            float s = 0.f;
#pragma unroll
            for (int p = 0; p < 16; p++) s += sh_cp[p * ENCn + tid];
            // scalar half store (odd half index -> half2 store would be misaligned)
            g_cat16[b * KC2 + 1 + tid] = __float2half(s);
        }
    }
}

// ---------------- K2: gates, single-shot panel, grid 4m x 16n x 4z = 256 blocks
// tile: cat[gm0:+64, gkb:+144] @ wcat[gn0:+64, gkb:+144]^T  (fp16 mma, fp32 acc)
#define LDS_G 144   // smem row stride in halfs (288B rows; ldsm addrs 16B aligned)
__global__ __launch_bounds__(256) void k_gates256() {
    __shared__ __half gAs[64 * LDS_G];
    __shared__ __half gBs[64 * LDS_G];
    int tid = threadIdx.x;
    int w = tid >> 5, l = tid & 31;
    int gm0 = blockIdx.x * 64, gn0 = blockIdx.y * 64;
    int gz = blockIdx.z, gkb = gz * KQ;
    int gwarp_m = w & 3, gwarp_n = w >> 2;      // 4m x 2n warps; warp tile 16m x 32n

    // single-shot panel load: 2304 uint4 (A 1152 + B 1152), 9 per thread, MLP ~9
#pragma unroll
    for (int it = 0; it < 9; it++) {
        int i = tid + 256 * it;
        int reg = i >= 1152;
        int j = reg ? i - 1152 : i;
        int r = j / 18, c = j % 18;
        const __half* src = reg
            ? g_wcat16 + (size_t)(gn0 + r) * KC2 + gkb + c * 8
            : g_cat16  + (size_t)(gm0 + r) * KC2 + gkb + c * 8;
        __half* dst = (reg ? gBs : gAs) + r * LDS_G + c * 8;
        *(uint4*)dst = *(const uint4*)src;
    }
    __syncthreads();

    float acc[4][4];
#pragma unroll
    for (int i = 0; i < 4; i++)
#pragma unroll
        for (int q = 0; q < 4; q++) acc[i][q] = 0.f;

#pragma unroll
    for (int ks = 0; ks < 9; ks++) {
        uint32_t a[4], bq[2][4];
        ldsm_x4(a, &gAs[(gwarp_m * 16 + (l & 15)) * LDS_G + ks * 16 + (l >> 4) * 8]);
#pragma unroll
        for (int bt = 0; bt < 2; bt++)
            ldsm_x4(bq[bt], &gBs[(gwarp_n * 32 + bt * 16 + (l & 15)) * LDS_G + ks * 16 + (l >> 4) * 8]);
#pragma unroll
        for (int bt = 0; bt < 2; bt++) {
            mma16816(acc[bt * 2 + 0], a, bq[bt][0], bq[bt][2]);   // n 0-7 of sub-tile
            mma16816(acc[bt * 2 + 1], a, bq[bt][1], bq[bt][3]);   // n 8-15
        }
    }

    float* Cg = g_gp + (size_t)gz * Bn * G4;
    int r0 = l >> 2, c0 = (l & 3) * 2;
#pragma unroll
    for (int nt = 0; nt < 4; nt++) {
        int gmr = gm0 + gwarp_m * 16 + r0;
        int gnc = gn0 + gwarp_n * 32 + (nt >> 1) * 16 + (nt & 1) * 8 + c0;
        *(float2*)&Cg[(size_t)gmr * G4 + gnc]       = make_float2(acc[nt][0], acc[nt][1]);
        *(float2*)&Cg[(size_t)(gmr + 8) * G4 + gnc] = make_float2(acc[nt][2], acc[nt][3]);
    }
}

// ---------------- K3: final cell for last step's preds ----------------
__global__ __launch_bounds__(256) void k_cell_final(const float* __restrict__ bih,
                                                    const float* __restrict__ bhh,
                                                    const float* __restrict__ Wout,
                                                    const float* __restrict__ bout,
                                                    float* __restrict__ out) {
    int b = blockIdx.x, d = threadIdx.x;
    float gi = bih[d]       + bhh[d];
    float gf = bih[d + 256] + bhh[d + 256];
    float gg = bih[d + 512] + bhh[d + 512];
    float go = bih[d + 768] + bhh[d + 768];
#pragma unroll
    for (int z = 0; z < NSPLIT; z++) {
        const float* gp = g_gp + (size_t)z * Bn * G4 + b * G4 + d;
        gi += gp[0]; gf += gp[256]; gg += gp[512]; go += gp[768];
    }
    float si = 1.f / (1.f + __expf(-gi));
    float sf = 1.f / (1.f + __expf(-gf));
    float so = 1.f / (1.f + __expf(-go));
    float cn = sf * g_c[b * DECn + d] + si * tanhf(gg);
    float hn = so * tanhf(cn);
    float p = hn * Wout[d];
    __shared__ float sred[8];
#pragma unroll
    for (int o = 16; o; o >>= 1) p += __shfl_xor_sync(0xFFFFFFFFu, p, o);
    if ((d & 31) == 0) sred[d >> 5] = p;
    __syncthreads();
    if (d == 0) {
        float s = 0.f;
#pragma unroll
        for (int i = 0; i < 8; i++) s += sred[i];
        out[b * Hn + (Hn - 1)] = s + bout[0];
    }
}

// ---------------- launch ----------------
extern "C" void kernel_launch(void* const* d_in, const int* in_sizes, int n_in,
                              void* d_out, int out_size) {
    (void)in_sizes; (void)n_in; (void)out_size;
    const float* enc  = (const float*)d_in[0];
    const float* h0   = (const float*)d_in[1];
    const float* c0   = (const float*)d_in[2];
    const float* Wenc = (const float*)d_in[3];
    const float* Wdec = (const float*)d_in[4];
    const float* v    = (const float*)d_in[5];
    const float* Wih  = (const float*)d_in[6];
    const float* Whh  = (const float*)d_in[7];
    const float* bih  = (const float*)d_in[8];
    const float* bhh  = (const float*)d_in[9];
    const float* Wout = (const float*)d_in[10];
    const float* bout = (const float*)d_in[11];
    float* out = (float*)d_out;

    k_init<<<2048, 256>>>(h0, c0, Wih, Whh, enc, Wenc, Wdec);
    k_encproj<<<(Bn * Sn) / 128, 256>>>();
    for (int t = 0; t < Hn; t++) {
        k_attn<<<Bn, 512>>>(v, bih, bhh, Wout, bout, out, t);
        k_gates256<<<dim3(4, 16, NSPLIT), 256>>>();
    }
    k_cell_final<<<Bn, 256>>>(bih, bhh, Wout, bout, out);
}

// round 17
// speedup vs baseline: 1.3568x; 1.3236x over previous
#include <cuda_runtime.h>
#include <cuda_fp16.h>
#include <math.h>
#include <stdint.h>

// Problem dims
#define Bn   256
#define Sn   512
#define ENCn 256
#define DECn 256
#define ATTNn 128
#define Hn   48
#define G4   1024          // 4*DEC
#define KIH  257           // 1+ENC
#define KC2  576           // 1 + 256 ctx + 256 h + 63 pad  (fp16 concat K)
#define KQ   144           // split-K quarter (9 k-steps of 16)
#define NSPLIT 4

// ---------------- scratch (device globals; no allocation) ----------------
__device__ __half g_enc16[(size_t)Bn * Sn * ENCn];   // fp16 enc_outputs
__device__ __half g_ep16[(size_t)Bn * Sn * ATTNn];   // fp16 enc_proj
__device__ __half g_wenc16[ENCn * ATTNn];            // fp16 W_enc [K][N]
__device__ __half g_wdec16[DECn * ATTNn];            // fp16 W_dec [K][N]
__device__ float  g_c[Bn * DECn];
__device__ __half g_cat16[Bn * KC2];                 // 0=inp, 1..256=ctx, 257..512=h, pad
__device__ __half g_wcat16[G4 * KC2];                // [W_ih | W_hh] fp16, zero-padded
__device__ float  g_gp[NSPLIT * Bn * G4];            // split-K fp32 partials

__device__ __forceinline__ float tanh_ap(float x) {
    float y;
    asm("tanh.approx.f32 %0, %1;" : "=f"(y) : "f"(x));
    return y;
}

// ---------------- mma helpers ----------------
__device__ __forceinline__ void ldsm_x4(uint32_t* r, const __half* p) {
    uint32_t a = (uint32_t)__cvta_generic_to_shared(p);
    asm volatile("ldmatrix.sync.aligned.m8n8.x4.shared.b16 {%0,%1,%2,%3}, [%4];"
                 : "=r"(r[0]), "=r"(r[1]), "=r"(r[2]), "=r"(r[3]) : "r"(a));
}
__device__ __forceinline__ void ldsm_x4_t(uint32_t* r, const __half* p) {
    uint32_t a = (uint32_t)__cvta_generic_to_shared(p);
    asm volatile("ldmatrix.sync.aligned.m8n8.x4.trans.shared.b16 {%0,%1,%2,%3}, [%4];"
                 : "=r"(r[0]), "=r"(r[1]), "=r"(r[2]), "=r"(r[3]) : "r"(a));
}
__device__ __forceinline__ void mma16816(float* d, const uint32_t* a, uint32_t b0, uint32_t b1) {
    asm volatile("mma.sync.aligned.m16n8k16.row.col.f32.f16.f16.f32 "
                 "{%0,%1,%2,%3}, {%4,%5,%6,%7}, {%8,%9}, {%0,%1,%2,%3};"
                 : "+f"(d[0]), "+f"(d[1]), "+f"(d[2]), "+f"(d[3])
                 : "r"(a[0]), "r"(a[1]), "r"(a[2]), "r"(a[3]), "r"(b0), "r"(b1));
}

// ---------------- init ----------------
__global__ void k_init(const float* __restrict__ h0, const float* __restrict__ c0,
                       const float* __restrict__ W_ih, const float* __restrict__ W_hh,
                       const float* __restrict__ enc, const float* __restrict__ Wenc,
                       const float* __restrict__ Wdec) {
    size_t i0 = (size_t)blockIdx.x * blockDim.x + threadIdx.x;
    size_t stride = (size_t)gridDim.x * blockDim.x;
    for (size_t i = i0; i < Bn * DECn; i += stride) g_c[i] = c0[i];
    for (size_t i = i0; i < (size_t)Bn * KC2; i += stride) {
        int b = (int)(i / KC2), k = (int)(i % KC2);
        float w = (k >= KIH && k < KIH + DECn) ? h0[b * DECn + (k - KIH)] : 0.f;
        g_cat16[i] = __float2half(w);
    }
    for (size_t i = i0; i < (size_t)G4 * KC2; i += stride) {
        int r = (int)(i / KC2), k = (int)(i % KC2);
        float w = 0.f;
        if (k < KIH) w = W_ih[r * KIH + k];
        else if (k < KIH + DECn) w = W_hh[r * DECn + (k - KIH)];
        g_wcat16[i] = __float2half(w);
    }
    for (size_t i = i0; i < (size_t)Bn * Sn * ENCn / 2; i += stride) {
        float2 f = *((const float2*)enc + i);
        *((__half2*)g_enc16 + i) = __floats2half2_rn(f.x, f.y);
    }
    for (size_t i = i0; i < (size_t)ENCn * ATTNn / 2; i += stride) {
        float2 f = *((const float2*)Wenc + i);
        *((__half2*)g_wenc16 + i) = __floats2half2_rn(f.x, f.y);
    }
    for (size_t i = i0; i < (size_t)DECn * ATTNn / 2; i += stride) {
        float2 f = *((const float2*)Wdec + i);
        *((__half2*)g_wdec16 + i) = __floats2half2_rn(f.x, f.y);
    }
}

// ---------------- K0: enc_proj via fp16 tensor cores ----------------
#define LDA 72    // As row stride (halfs)
#define LDB 136   // Bs row stride (halfs)
__global__ __launch_bounds__(256) void k_encproj() {
    __shared__ __half As[128 * LDA];
    __shared__ __half Bs[64 * LDB];
    int tid = threadIdx.x;
    int wid = tid >> 5, l = tid & 31;
    int warp_m = wid & 3, warp_n = wid >> 2;       // 4 x 2 warps; warp tile 32m x 64n
    size_t m0 = (size_t)blockIdx.x * 128;

    float acc[2][8][4];
#pragma unroll
    for (int i = 0; i < 2; i++)
#pragma unroll
        for (int j = 0; j < 8; j++)
#pragma unroll
            for (int q = 0; q < 4; q++) acc[i][j][q] = 0.f;

    for (int kc = 0; kc < 4; kc++) {
#pragma unroll
        for (int it = 0; it < 4; it++) {
            int i = tid + 256 * it;
            int r = i >> 3, c = (i & 7) * 8;
            *(uint4*)&As[r * LDA + c] = *(const uint4*)&g_enc16[(m0 + r) * ENCn + kc * 64 + c];
        }
#pragma unroll
        for (int it = 0; it < 4; it++) {
            int i = tid + 256 * it;
            int r = i >> 4, c = (i & 15) * 8;
            *(uint4*)&Bs[r * LDB + c] = *(const uint4*)&g_wenc16[(size_t)(kc * 64 + r) * ATTNn + c];
        }
        __syncthreads();
#pragma unroll
        for (int ks = 0; ks < 4; ks++) {
            uint32_t a[2][4];
#pragma unroll
            for (int mt = 0; mt < 2; mt++)
                ldsm_x4(a[mt], &As[(warp_m * 32 + mt * 16 + (l & 15)) * LDA + ks * 16 + (l >> 4) * 8]);
            uint32_t bf[4][4];
#pragma unroll
            for (int pr = 0; pr < 4; pr++)
                ldsm_x4_t(bf[pr], &Bs[(ks * 16 + (l & 15)) * LDB + warp_n * 64 + pr * 16 + (l >> 4) * 8]);
#pragma unroll
            for (int mt = 0; mt < 2; mt++)
#pragma unroll
                for (int nt = 0; nt < 8; nt++)
                    mma16816(acc[mt][nt], a[mt], bf[nt >> 1][(nt & 1) * 2], bf[nt >> 1][(nt & 1) * 2 + 1]);
        }
        __syncthreads();
    }
    int r0 = l >> 2, c0 = (l & 3) * 2;
#pragma unroll
    for (int mt = 0; mt < 2; mt++)
#pragma unroll
        for (int nt = 0; nt < 8; nt++) {
            size_t gm = m0 + warp_m * 32 + mt * 16 + r0;
            int gn = warp_n * 64 + nt * 8 + c0;
            *(__half2*)&g_ep16[gm * ATTNn + gn]       = __floats2half2_rn(acc[mt][nt][0], acc[mt][nt][1]);
            *(__half2*)&g_ep16[(gm + 8) * ATTNn + gn] = __floats2half2_rn(acc[mt][nt][2], acc[mt][nt][3]);
        }
}

// ---------------- K1: fused [cell(t-1)] + attention(t), one block per batch b
__global__ __launch_bounds__(512, 2) void k_attn(const float* __restrict__ v,
                                                 const float* __restrict__ bih,
                                                 const float* __restrict__ bhh,
                                                 const float* __restrict__ Wout,
                                                 const float* __restrict__ bout,
                                                 float* __restrict__ out, int t) {
    int b = blockIdx.x;
    int tid = threadIdx.x;
    __shared__ float sh_h[DECn];
    __shared__ float sh_dpp[8][ATTNn];
    __shared__ float sh_dp[ATTNn];
    __shared__ float sh_v[ATTNn];
    __shared__ float sh_sc[Sn];
    __shared__ float sh_red[32];
    __shared__ float sh_cp[16 * ENCn];   // context partials: 16 s-parts x 256 dims

    // ---- fused LSTM cell for step t-1 ----
    if (t > 0) {
        if (tid < DECn) {
            int d = tid;
            float gi = bih[d]       + bhh[d];
            float gf = bih[d + 256] + bhh[d + 256];
            float gg = bih[d + 512] + bhh[d + 512];
            float go = bih[d + 768] + bhh[d + 768];
#pragma unroll
            for (int z = 0; z < NSPLIT; z++) {
                const float* gp = g_gp + (size_t)z * Bn * G4 + b * G4 + d;
                gi += gp[0]; gf += gp[256]; gg += gp[512]; go += gp[768];
            }
            float si = 1.f / (1.f + __expf(-gi));
            float sf = 1.f / (1.f + __expf(-gf));
            float so = 1.f / (1.f + __expf(-go));
            float cn = sf * g_c[b * DECn + d] + si * tanhf(gg);
            float hn = so * tanhf(cn);
            g_c[b * DECn + d] = cn;
            sh_h[d] = hn;
            g_cat16[b * KC2 + KIH + d] = __float2half(hn);
            float p = hn * Wout[d];
#pragma unroll
            for (int o = 16; o; o >>= 1) p += __shfl_xor_sync(0xFFFFFFFFu, p, o);
            if ((d & 31) == 0) sh_red[d >> 5] = p;
        }
        __syncthreads();
        if (tid == 0) {
            float s = 0.f;
#pragma unroll
            for (int i = 0; i < 8; i++) s += sh_red[i];
            s += bout[0];
            out[b * Hn + (t - 1)] = s;
            g_cat16[b * KC2] = __float2half(s);
        }
    } else {
        if (tid < DECn) sh_h[tid] = __half2float(g_cat16[b * KC2 + KIH + tid]);
    }
    if (tid < ATTNn) sh_v[tid] = v[tid];
    __syncthreads();

    // ---- dec_proj = h @ W_dec (fp16 weights, 8-way K split, 2 cols/thread) ----
    {
        int c2 = (tid & 63) * 2, part = tid >> 6;       // part 0..7, 32 k each
        float2 a = make_float2(0.f, 0.f);
#pragma unroll 8
        for (int k = part * 32; k < part * 32 + 32; k++) {
            float2 w = __half22float2(*(const __half2*)&g_wdec16[k * ATTNn + c2]);
            float hk = sh_h[k];
            a.x = fmaf(hk, w.x, a.x);
            a.y = fmaf(hk, w.y, a.y);
        }
        sh_dpp[part][c2] = a.x; sh_dpp[part][c2 + 1] = a.y;
    }
    __syncthreads();
    if (tid < ATTNn) {
        float s = 0.f;
#pragma unroll
        for (int i = 0; i < 8; i++) s += sh_dpp[i][tid];
        sh_dp[tid] = s;
    }
    __syncthreads();

    // ---- scores (fp32 tanh): warp handles 2 s per pass; 16 lanes x 8 dims; prefetched ----
    int w = tid >> 5, l = tid & 31;
    {
        int sgrp = l >> 4;            // which of 2 s in this pass
        int dlo = (l & 15) * 8;       // my 8 attn dims
        float dpr[8], vr[8];
        *(float4*)&dpr[0] = *(float4*)&sh_dp[dlo];
        *(float4*)&dpr[4] = *(float4*)&sh_dp[dlo + 4];
        *(float4*)&vr[0]  = *(float4*)&sh_v[dlo];
        *(float4*)&vr[4]  = *(float4*)&sh_v[dlo + 4];
        const __half* epb = g_ep16 + (size_t)b * Sn * ATTNn + dlo;

        int s = w * 2 + sgrp;
        uint4 u = *(const uint4*)(epb + (size_t)s * ATTNn);
#pragma unroll
        for (int p = 0; p < 16; p++) {
            uint4 un;
            if (p < 15) un = *(const uint4*)(epb + (size_t)(s + 32) * ATTNn);   // prefetch next pass
            const __half2* hp = (const __half2*)&u;
            float sc = 0.f;
#pragma unroll
            for (int j = 0; j < 4; j++) {
                float2 f = __half22float2(hp[j]);
                sc = fmaf(tanh_ap(f.x + dpr[2 * j]),     vr[2 * j],     sc);
                sc = fmaf(tanh_ap(f.y + dpr[2 * j + 1]), vr[2 * j + 1], sc);
            }
            sc += __shfl_xor_sync(0xFFFFFFFFu, sc, 8);
            sc += __shfl_xor_sync(0xFFFFFFFFu, sc, 4);
            sc += __shfl_xor_sync(0xFFFFFFFFu, sc, 2);
            sc += __shfl_xor_sync(0xFFFFFFFFu, sc, 1);
            if ((l & 15) == 0) sh_sc[s] = sc;
            u = un;
            s += 32;
        }
    }
    __syncthreads();

    // ---- softmax over 512 (scores bounded by sum|v| ~ 5; no max pass needed) ----
    float e = __expf(sh_sc[tid]);
    float ssum = e;
#pragma unroll
    for (int o = 16; o; o >>= 1) ssum += __shfl_xor_sync(0xFFFFFFFFu, ssum, o);
    if (l == 0) sh_red[w] = ssum;
    __syncthreads();
    float tot = 0.f;
#pragma unroll
    for (int i = 0; i < 16; i++) tot += sh_red[i];
    float wgt = e / tot;
    sh_sc[tid] = wgt;
    out[(size_t)Bn * Hn + ((size_t)b * Hn + t) * Sn + tid] = wgt;
    __syncthreads();

    // ---- context = attn_w @ enc_outputs: 8 dims/thread (LDG.128), 16-way s split,
    //      fp32 accumulation, cross-part reduce via smem ----
    {
        int dg = tid & 31;            // dim group: dims 8*dg .. 8*dg+7
        int part = tid >> 5;          // warp id = s-part 0..15
        const __half* eb = g_enc16 + (size_t)b * Sn * ENCn + 8 * dg;
        float a[8];
#pragma unroll
        for (int i = 0; i < 8; i++) a[i] = 0.f;
#pragma unroll 8
        for (int s = part; s < Sn; s += 16) {
            uint4 u = *(const uint4*)(eb + (size_t)s * ENCn);
            float ww = sh_sc[s];
            const __half2* hp = (const __half2*)&u;
#pragma unroll
            for (int j = 0; j < 4; j++) {
                float2 f = __half22float2(hp[j]);
                a[2 * j]     = fmaf(ww, f.x, a[2 * j]);
                a[2 * j + 1] = fmaf(ww, f.y, a[2 * j + 1]);
            }
        }
        float* cp = sh_cp + part * ENCn + dg * 8;
#pragma unroll
        for (int i = 0; i < 8; i++) cp[i] = a[i];
        __syncthreads();
        if (tid < ENCn) {
            float s = 0.f;
#pragma unroll
            for (int p = 0; p < 16; p++) s += sh_cp[p * ENCn + tid];
            // scalar half store (odd half index -> half2 store would be misaligned)
            g_cat16[b * KC2 + 1 + tid] = __float2half(s);
        }
    }
}

// ---------------- K2: gates, single-shot panel, grid 4m x 16n x 4z = 256 blocks
// tile: cat[gm0:+64, gkb:+144] @ wcat[gn0:+64, gkb:+144]^T  (fp16 mma, fp32 acc)
#define LDS_G 144   // smem row stride in halfs (288B rows; ldsm addrs 16B aligned)
__global__ __launch_bounds__(256) void k_gates256() {
    __shared__ __half gAs[64 * LDS_G];
    __shared__ __half gBs[64 * LDS_G];
    int tid = threadIdx.x;
    int w = tid >> 5, l = tid & 31;
    int gm0 = blockIdx.x * 64, gn0 = blockIdx.y * 64;
    int gz = blockIdx.z, gkb = gz * KQ;
    int gwarp_m = w & 3, gwarp_n = w >> 2;      // 4m x 2n warps; warp tile 16m x 32n

    // single-shot panel load: 2304 uint4 (A 1152 + B 1152), 9 per thread, MLP ~9
#pragma unroll
    for (int it = 0; it < 9; it++) {
        int i = tid + 256 * it;
        int reg = i >= 1152;
        int j = reg ? i - 1152 : i;
        int r = j / 18, c = j % 18;
        const __half* src = reg
            ? g_wcat16 + (size_t)(gn0 + r) * KC2 + gkb + c * 8
            : g_cat16  + (size_t)(gm0 + r) * KC2 + gkb + c * 8;
        __half* dst = (reg ? gBs : gAs) + r * LDS_G + c * 8;
        *(uint4*)dst = *(const uint4*)src;
    }
    __syncthreads();

    float acc[4][4];
#pragma unroll
    for (int i = 0; i < 4; i++)
#pragma unroll
        for (int q = 0; q < 4; q++) acc[i][q] = 0.f;

#pragma unroll
    for (int ks = 0; ks < 9; ks++) {
        uint32_t a[4], bq[2][4];
        ldsm_x4(a, &gAs[(gwarp_m * 16 + (l & 15)) * LDS_G + ks * 16 + (l >> 4) * 8]);
#pragma unroll
        for (int bt = 0; bt < 2; bt++)
            ldsm_x4(bq[bt], &gBs[(gwarp_n * 32 + bt * 16 + (l & 15)) * LDS_G + ks * 16 + (l >> 4) * 8]);
#pragma unroll
        for (int bt = 0; bt < 2; bt++) {
            mma16816(acc[bt * 2 + 0], a, bq[bt][0], bq[bt][2]);   // n 0-7 of sub-tile
            mma16816(acc[bt * 2 + 1], a, bq[bt][1], bq[bt][3]);   // n 8-15
        }
    }

    float* Cg = g_gp + (size_t)gz * Bn * G4;
    int r0 = l >> 2, c0 = (l & 3) * 2;
#pragma unroll
    for (int nt = 0; nt < 4; nt++) {
        int gmr = gm0 + gwarp_m * 16 + r0;
        int gnc = gn0 + gwarp_n * 32 + (nt >> 1) * 16 + (nt & 1) * 8 + c0;
        *(float2*)&Cg[(size_t)gmr * G4 + gnc]       = make_float2(acc[nt][0], acc[nt][1]);
        *(float2*)&Cg[(size_t)(gmr + 8) * G4 + gnc] = make_float2(acc[nt][2], acc[nt][3]);
    }
}

// ---------------- K3: final cell for last step's preds ----------------
__global__ __launch_bounds__(256) void k_cell_final(const float* __restrict__ bih,
                                                    const float* __restrict__ bhh,
                                                    const float* __restrict__ Wout,
                                                    const float* __restrict__ bout,
                                                    float* __restrict__ out) {
    int b = blockIdx.x, d = threadIdx.x;
    float gi = bih[d]       + bhh[d];
    float gf = bih[d + 256] + bhh[d + 256];
    float gg = bih[d + 512] + bhh[d + 512];
    float go = bih[d + 768] + bhh[d + 768];
#pragma unroll
    for (int z = 0; z < NSPLIT; z++) {
        const float* gp = g_gp + (size_t)z * Bn * G4 + b * G4 + d;
        gi += gp[0]; gf += gp[256]; gg += gp[512]; go += gp[768];
    }
    float si = 1.f / (1.f + __expf(-gi));
    float sf = 1.f / (1.f + __expf(-gf));
    float so = 1.f / (1.f + __expf(-go));
    float cn = sf * g_c[b * DECn + d] + si * tanhf(gg);
    float hn = so * tanhf(cn);
    float p = hn * Wout[d];
    __shared__ float sred[8];
#pragma unroll
    for (int o = 16; o; o >>= 1) p += __shfl_xor_sync(0xFFFFFFFFu, p, o);
    if ((d & 31) == 0) sred[d >> 5] = p;
    __syncthreads();
    if (d == 0) {
        float s = 0.f;
#pragma unroll
        for (int i = 0; i < 8; i++) s += sred[i];
        out[b * Hn + (Hn - 1)] = s + bout[0];
    }
}

// ---------------- launch ----------------
extern "C" void kernel_launch(void* const* d_in, const int* in_sizes, int n_in,
                              void* d_out, int out_size) {
    (void)in_sizes; (void)n_in; (void)out_size;
    const float* enc  = (const float*)d_in[0];
    const float* h0   = (const float*)d_in[1];
    const float* c0   = (const float*)d_in[2];
    const float* Wenc = (const float*)d_in[3];
    const float* Wdec = (const float*)d_in[4];
    const float* v    = (const float*)d_in[5];
    const float* Wih  = (const float*)d_in[6];
    const float* Whh  = (const float*)d_in[7];
    const float* bih  = (const float*)d_in[8];
    const float* bhh  = (const float*)d_in[9];
    const float* Wout = (const float*)d_in[10];
    const float* bout = (const float*)d_in[11];
    float* out = (float*)d_out;

    k_init<<<2048, 256>>>(h0, c0, Wih, Whh, enc, Wenc, Wdec);
    k_encproj<<<(Bn * Sn) / 128, 256>>>();
    for (int t = 0; t < Hn; t++) {
        k_attn<<<Bn, 512>>>(v, bih, bhh, Wout, bout, out, t);
        k_gates256<<<dim3(4, 16, NSPLIT), 256>>>();
    }
    k_cell_final<<<Bn, 256>>>(bih, bhh, Wout, bout, out);
}